// round 1
// baseline (speedup 1.0000x reference)
#include <cuda_runtime.h>

#define KN 40
#define FN 32
#define WPB 8
#define WSTRIDE 448  // floats of smem per warp (1792B, 16B aligned)

__device__ __forceinline__ unsigned long long pack2(float lo, float hi) {
    unsigned long long r;
    asm("mov.b64 %0, {%1,%2};" : "=l"(r) : "f"(lo), "f"(hi));
    return r;
}
__device__ __forceinline__ void unpack2(unsigned long long v, float& lo, float& hi) {
    asm("mov.b64 {%0,%1}, %2;" : "=f"(lo), "=f"(hi) : "l"(v));
}
__device__ __forceinline__ unsigned long long ffma2(unsigned long long a,
                                                    unsigned long long b,
                                                    unsigned long long c) {
    unsigned long long d;
    asm("fma.rn.f32x2 %0, %1, %2, %3;" : "=l"(d) : "l"(a), "l"(b), "l"(c));
    return d;
}

__global__ __launch_bounds__(WPB * 32)
void nbcov_kernel(const float* __restrict__ coords,
                  const float* __restrict__ distsq,
                  const float* __restrict__ feats,
                  const int* __restrict__ nidx,
                  float* __restrict__ out, int V)
{
    __shared__ float smem[WPB * WSTRIDE];
    const int warp = threadIdx.x >> 5;
    const int lane = threadIdx.x & 31;
    const int v = blockIdx.x * WPB + warp;
    if (v >= V) return;

    float* ws = smem + warp * WSTRIDE;
    // phase-1 layout: [0,160) wmA float4[40], [160,320) wmB float4[40],
    //                 [320,400) wmC float2[40], [400,440) fbase int[40]
    float4* wmA = (float4*)ws;
    float4* wmB = (float4*)(ws + 160);
    float2* wmC = (float2*)(ws + 320);
    int*    fb  = (int*)(ws + 400);

    // ---- prep: each lane computes weighted moment vector for k=lane (+ k=32+lane for lane<8)
    {
        const int ko = v * KN + lane;
        int ia = nidx[ko];
        float da = distsq[ko];
        float wa = (ia >= 0) ? __expf(-10.0f * da) : 0.0f;
        if (ia < 0) ia = 0;
        float x = coords[ia * 3 + 0];
        float y = coords[ia * 3 + 1];
        float z = coords[ia * 3 + 2];
        float m1 = wa * x, m2 = wa * y, m3 = wa * z;
        wmA[lane] = make_float4(wa, m1, m2, m3);              // S0,S1 | S2,S3
        wmB[lane] = make_float4(m1 * x, m1 * y, m1 * z, m2 * y); // xx,xy | xz,yy
        wmC[lane] = make_float2(m2 * z, m3 * z);              // yz,zz
        fb[lane] = ia * FN;
        if (lane < 8) {
            const int k = 32 + lane;
            const int ko2 = v * KN + k;
            int ib = nidx[ko2];
            float db = distsq[ko2];
            float wb = (ib >= 0) ? __expf(-10.0f * db) : 0.0f;
            if (ib < 0) ib = 0;
            float xb = coords[ib * 3 + 0];
            float yb = coords[ib * 3 + 1];
            float zb = coords[ib * 3 + 2];
            float n1 = wb * xb, n2 = wb * yb, n3 = wb * zb;
            wmA[k] = make_float4(wb, n1, n2, n3);
            wmB[k] = make_float4(n1 * xb, n1 * yb, n1 * zb, n2 * yb);
            wmC[k] = make_float2(n2 * zb, n3 * zb);
            fb[k] = ib * FN;
        }
    }
    __syncwarp();

    // ---- main loop: lane = feature channel; 5 packed f32x2 FMAs per neighbor
    unsigned long long P0 = 0, P1 = 0, P2 = 0, P3 = 0, P4 = 0;
    #pragma unroll 8
    for (int k = 0; k < KN; ++k) {
        float f = feats[fb[k] + lane];                 // coalesced 128B gather (L2-resident)
        ulonglong2 a = *(const ulonglong2*)&wmA[k];    // LDS.128 broadcast
        ulonglong2 b = *(const ulonglong2*)&wmB[k];    // LDS.128 broadcast
        unsigned long long c = *(const unsigned long long*)&wmC[k]; // LDS.64
        unsigned long long ff = pack2(f, f);
        P0 = ffma2(ff, a.x, P0);   // S0 += f*w,   S1 += f*w*x
        P1 = ffma2(ff, a.y, P1);   // S2 += f*w*y, S3 += f*w*z
        P2 = ffma2(ff, b.x, P2);   // S4 += f*w*xx, S5 += f*w*xy
        P3 = ffma2(ff, b.y, P3);   // S6 += f*w*xz, S7 += f*w*yy
        P4 = ffma2(ff, c,   P4);   // S8 += f*w*yz, S9 += f*w*zz
    }
    __syncwarp();  // everyone done reading WM region before reuse as staging

    // ---- epilogue: normalize, center, stage for coalesced stores
    float S0, S1, S2, S3, S4, S5, S6, S7, S8, S9;
    unpack2(P0, S0, S1);
    unpack2(P1, S2, S3);
    unpack2(P2, S4, S5);
    unpack2(P3, S6, S7);
    unpack2(P4, S8, S9);

    float inv = __fdividef(1.0f, S0 + 1e-3f);
    float mx = S1 * inv, my = S2 * inv, mz = S3 * inv;
    float c00 = fmaf(-mx, mx, S4 * inv);
    float c01 = fmaf(-mx, my, S5 * inv);
    float c02 = fmaf(-mx, mz, S6 * inv);
    float c11 = fmaf(-my, my, S7 * inv);
    float c12 = fmaf(-my, mz, S8 * inv);
    float c22 = fmaf(-mz, mz, S9 * inv);

    {
        float* st = ws;               // 384-float staging, bank-conflict-free (stride 9 vs 32 coprime)
        const int bf = lane * 9;
        st[bf + 0] = c00; st[bf + 1] = c01; st[bf + 2] = c02;
        st[bf + 3] = c01; st[bf + 4] = c11; st[bf + 5] = c12;
        st[bf + 6] = c02; st[bf + 7] = c12; st[bf + 8] = c22;
        st[288 + lane * 3 + 0] = mx;
        st[288 + lane * 3 + 1] = my;
        st[288 + lane * 3 + 2] = mz;
    }
    __syncwarp();

    float4* o4 = (float4*)(out + (size_t)v * 384);
    const float4* s4 = (const float4*)ws;
    o4[lane]      = s4[lane];
    o4[lane + 32] = s4[lane + 32];
    o4[lane + 64] = s4[lane + 64];
}

extern "C" void kernel_launch(void* const* d_in, const int* in_sizes, int n_in,
                              void* d_out, int out_size) {
    const float* coords = (const float*)d_in[0];   // V x 3
    const float* distsq = (const float*)d_in[1];   // V x 40
    const float* feats  = (const float*)d_in[2];   // V x 32
    const int*   nidx   = (const int*)d_in[3];     // V x 40
    float* out = (float*)d_out;                    // V x 384
    const int V = in_sizes[0] / 3;
    const int blocks = (V + WPB - 1) / WPB;
    nbcov_kernel<<<blocks, WPB * 32>>>(coords, distsq, feats, nidx, out, V);
}

// round 2
// speedup vs baseline: 1.2045x; 1.2045x over previous
#include <cuda_runtime.h>

#define KN 40
#define FN 32
#define VPW 4                 // vertices per warp
#define WPB 4                 // warps per block
#define KREC 12               // floats per k-record (48B, 16B aligned)
#define VREC (KN*KREC + 8)    // 488 floats per vertex region; 488 % 32 == 8
#define WSH (VPW*VREC)        // 1952 floats per warp
#define SSTR 387              // epilogue staging stride (mod 32 == 3) -> conflict-free

__device__ float4 g_coords4[131072];   // padded coords scratch (V <= 131072)

__device__ __forceinline__ unsigned long long pack2(float lo, float hi) {
    unsigned long long r;
    asm("mov.b64 %0, {%1,%2};" : "=l"(r) : "f"(lo), "f"(hi));
    return r;
}
__device__ __forceinline__ void unpack2(unsigned long long v, float& lo, float& hi) {
    asm("mov.b64 {%0,%1}, %2;" : "=f"(lo), "=f"(hi) : "l"(v));
}
__device__ __forceinline__ unsigned long long ffma2(unsigned long long a,
                                                    unsigned long long b,
                                                    unsigned long long c) {
    unsigned long long d;
    asm("fma.rn.f32x2 %0, %1, %2, %3;" : "=l"(d) : "l"(a), "l"(b), "l"(c));
    return d;
}

__global__ void pad_coords_kernel(const float* __restrict__ c, int V) {
    int i = blockIdx.x * blockDim.x + threadIdx.x;
    if (i < V) {
        g_coords4[i] = make_float4(c[3*i], c[3*i+1], c[3*i+2], 0.f);
    }
}

__global__ __launch_bounds__(WPB * 32)
void nbcov_kernel(const float* __restrict__ distsq,
                  const float* __restrict__ feats,
                  const int* __restrict__ nidx,
                  float* __restrict__ out, int V)
{
    __shared__ float smem[WPB * WSH];
    const int warp = threadIdx.x >> 5;
    const int lane = threadIdx.x & 31;
    const int vbase = (blockIdx.x * WPB + warp) * VPW;
    float* ws = smem + warp * WSH;

    // ---------- prep: 160 (vertex,k) tasks per warp; build 12-float k-records ----------
    #pragma unroll
    for (int t = 0; t < 5; ++t) {
        const int id = t * 32 + lane;          // 0..159
        const int vloc = id / KN;
        const int k = id - vloc * KN;
        const int v = vbase + vloc;
        float w = 0.f;
        int ia = 0;
        float4 c4 = make_float4(0.f, 0.f, 0.f, 0.f);
        if (v < V) {
            const int ko = v * KN + k;
            int t_ia = nidx[ko];
            float d = distsq[ko];
            if (t_ia >= 0) {
                w = __expf(-10.0f * d);
                ia = t_ia;
            }
            c4 = g_coords4[ia];                // single LDG.128 gather
        }
        const float wx = w * c4.x, wy = w * c4.y, wz = w * c4.z;
        float* r = ws + vloc * VREC + k * KREC;
        *(float4*)(r)     = make_float4(w, wx, wy, wz);
        *(float4*)(r + 4) = make_float4(wx * c4.x, wx * c4.y, wx * c4.z, wy * c4.y);
        *(float4*)(r + 8) = make_float4(wy * c4.z, wz * c4.z,
                                        __int_as_float(ia * FN), 0.f);
    }
    __syncwarp();

    // ---------- main loop: 8-lane group g handles vertex vbase+g, 4 features/lane ----------
    const int g = lane >> 3;
    const int sub = lane & 7;
    const float* rec = ws + g * VREC;
    const float* fptr = feats + sub * 4;

    unsigned long long P[4][5];
    #pragma unroll
    for (int c = 0; c < 4; ++c)
        #pragma unroll
        for (int j = 0; j < 5; ++j) P[c][j] = 0ull;

    #pragma unroll 8
    for (int k = 0; k < KN; ++k) {
        const ulonglong2 A = *(const ulonglong2*)(rec + k * KREC);      // (w,wx)|(wy,wz)
        const ulonglong2 B = *(const ulonglong2*)(rec + k * KREC + 4);  // (wxx,wxy)|(wxz,wyy)
        const ulonglong2 E = *(const ulonglong2*)(rec + k * KREC + 8);  // (wyz,wzz)|(fb,pad)
        const int fb = (int)E.y;                                        // low 32 bits = ia*32
        const float4 f4 = *(const float4*)(fptr + fb);                  // LDG.128, 4 features

        unsigned long long d0 = pack2(f4.x, f4.x);
        unsigned long long d1 = pack2(f4.y, f4.y);
        unsigned long long d2 = pack2(f4.z, f4.z);
        unsigned long long d3 = pack2(f4.w, f4.w);

        P[0][0] = ffma2(d0, A.x, P[0][0]);
        P[0][1] = ffma2(d0, A.y, P[0][1]);
        P[0][2] = ffma2(d0, B.x, P[0][2]);
        P[0][3] = ffma2(d0, B.y, P[0][3]);
        P[0][4] = ffma2(d0, E.x, P[0][4]);

        P[1][0] = ffma2(d1, A.x, P[1][0]);
        P[1][1] = ffma2(d1, A.y, P[1][1]);
        P[1][2] = ffma2(d1, B.x, P[1][2]);
        P[1][3] = ffma2(d1, B.y, P[1][3]);
        P[1][4] = ffma2(d1, E.x, P[1][4]);

        P[2][0] = ffma2(d2, A.x, P[2][0]);
        P[2][1] = ffma2(d2, A.y, P[2][1]);
        P[2][2] = ffma2(d2, B.x, P[2][2]);
        P[2][3] = ffma2(d2, B.y, P[2][3]);
        P[2][4] = ffma2(d2, E.x, P[2][4]);

        P[3][0] = ffma2(d3, A.x, P[3][0]);
        P[3][1] = ffma2(d3, A.y, P[3][1]);
        P[3][2] = ffma2(d3, B.x, P[3][2]);
        P[3][3] = ffma2(d3, B.y, P[3][3]);
        P[3][4] = ffma2(d3, E.x, P[3][4]);
    }
    __syncwarp();   // records no longer needed; reuse smem as staging

    // ---------- epilogue: normalize + center, stage conflict-free, coalesced store ----------
    float* st = ws;   // staging: per-vertex stride SSTR (=387)
    #pragma unroll
    for (int c = 0; c < 4; ++c) {
        float S0, S1, S2, S3, S4, S5, S6, S7, S8, S9;
        unpack2(P[c][0], S0, S1);
        unpack2(P[c][1], S2, S3);
        unpack2(P[c][2], S4, S5);
        unpack2(P[c][3], S6, S7);
        unpack2(P[c][4], S8, S9);

        const float inv = __fdividef(1.0f, S0 + 1e-3f);
        const float mx = S1 * inv, my = S2 * inv, mz = S3 * inv;
        const float c00 = fmaf(-mx, mx, S4 * inv);
        const float c01 = fmaf(-mx, my, S5 * inv);
        const float c02 = fmaf(-mx, mz, S6 * inv);
        const float c11 = fmaf(-my, my, S7 * inv);
        const float c12 = fmaf(-my, mz, S8 * inv);
        const float c22 = fmaf(-mz, mz, S9 * inv);

        const int f = sub * 4 + c;
        float* dst = st + g * SSTR;
        dst[f * 9 + 0] = c00; dst[f * 9 + 1] = c01; dst[f * 9 + 2] = c02;
        dst[f * 9 + 3] = c01; dst[f * 9 + 4] = c11; dst[f * 9 + 5] = c12;
        dst[f * 9 + 6] = c02; dst[f * 9 + 7] = c12; dst[f * 9 + 8] = c22;
        dst[288 + f * 3 + 0] = mx;
        dst[288 + f * 3 + 1] = my;
        dst[288 + f * 3 + 2] = mz;
    }
    __syncwarp();

    // copy 4 vertices x 384 floats = 12 rounds of warp-wide float4 stores
    float* outp = out + (size_t)vbase * 384;
    #pragma unroll
    for (int r = 0; r < 12; ++r) {
        const int e = r * 128 + lane * 4;     // flat index into warp's 1536 outputs
        const int gv = e / 384;               // vertex within warp
        const int em = e - gv * 384;
        if (vbase + gv < V) {
            float4 val;
            val.x = st[gv * SSTR + em + 0];
            val.y = st[gv * SSTR + em + 1];
            val.z = st[gv * SSTR + em + 2];
            val.w = st[gv * SSTR + em + 3];
            *(float4*)(outp + e) = val;
        }
    }
}

extern "C" void kernel_launch(void* const* d_in, const int* in_sizes, int n_in,
                              void* d_out, int out_size) {
    const float* coords = (const float*)d_in[0];   // V x 3
    const float* distsq = (const float*)d_in[1];   // V x 40
    const float* feats  = (const float*)d_in[2];   // V x 32
    const int*   nidx   = (const int*)d_in[3];     // V x 40
    float* out = (float*)d_out;                    // V x 384
    const int V = in_sizes[0] / 3;

    pad_coords_kernel<<<(V + 255) / 256, 256>>>(coords, V);

    const int vpb = VPW * WPB;                     // 16 vertices per block
    nbcov_kernel<<<(V + vpb - 1) / vpb, WPB * 32>>>(distsq, feats, nidx, out, V);
}